// round 12
// baseline (speedup 1.0000x reference)
#include <cuda_runtime.h>
#include <math_constants.h>

// PhiCell hysteresis scan: out_i = clamp(out_{i-1}, x_i, x_i + 1), x_i = in_i*k.
// Clamp maps compose associatively -> single-pass scan, 67 MB total DRAM.
// R11: AGG-only fully-parallel lookback (no PRE chain, no serial windows):
// 512 threads read up to 4 contiguous predecessor aggregates each, ordered
// tree compose. Input kept in registers across lookback -> no second read.

#define BLOCK 512
#define ITEMS 8
#define CHUNK (BLOCK * ITEMS)     // 4096 elements per tile
#define MAXB  2048
#define PPT   (MAXB / BLOCK)      // predecessors per thread = 4

#define FLAG_INV 0
#define FLAG_AGG 1

struct CH { float L, H; };

__device__ __forceinline__ CH ch_id() {
    CH r; r.L = -CUDART_INF_F; r.H = CUDART_INF_F; return r;
}
// compose: apply a FIRST, then b
__device__ __forceinline__ CH ch_comp(CH a, CH b) {
    CH r;
    r.L = fminf(fmaxf(a.L, b.L), b.H);
    r.H = fminf(fmaxf(a.H, b.L), b.H);
    return r;
}

__device__ float2 g_agg[MAXB];
__device__ int    g_flag[MAXB];

__device__ __forceinline__ void st_flag_release(int i, int f) {
    asm volatile("st.global.release.gpu.b32 [%0], %1;"
                 :: "l"(&g_flag[i]), "r"(f) : "memory");
}
__device__ __forceinline__ int ld_flag_acquire(int i) {
    int f;
    asm volatile("ld.global.acquire.gpu.b32 %0, [%1];"
                 : "=r"(f) : "l"(&g_flag[i]) : "memory");
    return f;
}

__device__ __forceinline__ CH warp_incl_scan(CH v, int lane) {
#pragma unroll
    for (int off = 1; off < 32; off <<= 1) {
        float pl = __shfl_up_sync(0xffffffffu, v.L, off);
        float ph = __shfl_up_sync(0xffffffffu, v.H, off);
        if (lane >= off) { CH p; p.L = pl; p.H = ph; v = ch_comp(p, v); }
    }
    return v;
}

// exclusive composite of all lower-threadIdx threads (identity for t==0)
__device__ CH block_excl_scan(CH v) {
    __shared__ CH ws[BLOCK / 32];
    int lane = threadIdx.x & 31;
    int wid  = threadIdx.x >> 5;

    CH vi = warp_incl_scan(v, lane);
    if (lane == 31) ws[wid] = vi;
    __syncthreads();
    if (wid == 0) {
        CH w = (lane < BLOCK / 32) ? ws[lane] : ch_id();
        w = warp_incl_scan(w, lane);
        if (lane < BLOCK / 32) ws[lane] = w;
    }
    __syncthreads();
    CH wp = (wid > 0) ? ws[wid - 1] : ch_id();

    float pl = __shfl_up_sync(0xffffffffu, vi.L, 1);
    float ph = __shfl_up_sync(0xffffffffu, vi.H, 1);
    CH ve = ch_id();
    if (lane > 0) { ve.L = pl; ve.H = ph; }
    return ch_comp(wp, ve);
}

// reset tile flags before each scan (graph replays reuse g_flag)
__global__ void k_reset(int nb) {
    int i = blockIdx.x * blockDim.x + threadIdx.x;
    if (i < nb) g_flag[i] = FLAG_INV;
}

__global__ void __launch_bounds__(BLOCK)
k_scan(const float* __restrict__ in, const float* __restrict__ kw,
       const float* __restrict__ stt, float* __restrict__ out,
       int n, int out_size) {
    __shared__ CH s_part[BLOCK / 32];
    __shared__ CH s_prefix;

    float k  = __ldg(kw);
    int bid  = blockIdx.x;
    int tid  = threadIdx.x;
    int base = bid * CHUNK + tid * ITEMS;
    const float4* p = reinterpret_cast<const float4*>(in + base);

    // ---- phase A: load (kept in registers), per-thread composite ----
    float4 xa = __ldg(&p[0]);
    float4 xb = __ldg(&p[1]);
    float x0 = xa.x * k, x1 = xa.y * k, x2 = xa.z * k, x3 = xa.w * k;
    float x4 = xb.x * k, x5 = xb.y * k, x6 = xb.z * k, x7 = xb.w * k;

    CH c = ch_id();
    {
        float a;
        a = x0; c.L = fminf(fmaxf(c.L, a), a + 1.0f); c.H = fminf(fmaxf(c.H, a), a + 1.0f);
        a = x1; c.L = fminf(fmaxf(c.L, a), a + 1.0f); c.H = fminf(fmaxf(c.H, a), a + 1.0f);
        a = x2; c.L = fminf(fmaxf(c.L, a), a + 1.0f); c.H = fminf(fmaxf(c.H, a), a + 1.0f);
        a = x3; c.L = fminf(fmaxf(c.L, a), a + 1.0f); c.H = fminf(fmaxf(c.H, a), a + 1.0f);
        a = x4; c.L = fminf(fmaxf(c.L, a), a + 1.0f); c.H = fminf(fmaxf(c.H, a), a + 1.0f);
        a = x5; c.L = fminf(fmaxf(c.L, a), a + 1.0f); c.H = fminf(fmaxf(c.H, a), a + 1.0f);
        a = x6; c.L = fminf(fmaxf(c.L, a), a + 1.0f); c.H = fminf(fmaxf(c.H, a), a + 1.0f);
        a = x7; c.L = fminf(fmaxf(c.L, a), a + 1.0f); c.H = fminf(fmaxf(c.H, a), a + 1.0f);
    }

    CH e = block_excl_scan(c);   // contains __syncthreads

    // publish tile aggregate (write-once + release flag)
    if (tid == BLOCK - 1) {
        CH t = ch_comp(e, c);
        g_agg[bid] = make_float2(t.L, t.H);
        st_flag_release(bid, FLAG_AGG);
    }

    // ---- lookback: ALL predecessors in one parallel shot ----
    // thread t covers 4 CONTIGUOUS predecessors: idx = bid-1-(4t+j), j=0..3
    // (contiguous partitioning keeps non-commutative composition ordered)
    int lane = tid & 31;
    int w    = tid >> 5;
    CH v = ch_id();
#pragma unroll
    for (int j = PPT - 1; j >= 0; j--) {      // j=3 earliest -> apply first
        int idx = bid - 1 - (tid * PPT + j);
        if (idx >= 0) {
            int f = ld_flag_acquire(idx);
            while (f == FLAG_INV) { __nanosleep(64); f = ld_flag_acquire(idx); }
            float2 a2 = g_agg[idx];
            CH b; b.L = a2.x; b.H = a2.y;     // tile idx, LATER than v so far
            v = ch_comp(v, b);
        }
    }
    // warp butterfly: lane+off holds EARLIER tiles -> apply first
#pragma unroll
    for (int off = 1; off < 32; off <<= 1) {
        float bl = __shfl_down_sync(0xffffffffu, v.L, off);
        float bh = __shfl_down_sync(0xffffffffu, v.H, off);
        if (lane + off < 32) { CH b; b.L = bl; b.H = bh; v = ch_comp(b, v); }
    }
    if (lane == 0) s_part[w] = v;
    __syncthreads();
    if (tid == 0) {
        CH acc = ch_id();
#pragma unroll
        for (int j = BLOCK / 32 - 1; j >= 0; j--)   // warp 15 earliest first
            acc = ch_comp(acc, s_part[j]);
        s_prefix = acc;
    }
    __syncthreads();

    // ---- phase B: outputs straight from registers ----
    CH my = ch_comp(s_prefix, e);
    float s0   = __ldg(stt);
    float prev = fminf(fmaxf(s0, my.L), my.H);   // = out[base-1]

    float4 r;
    float4* o = reinterpret_cast<float4*>(out + base);
    prev = fminf(fmaxf(prev, x0), x0 + 1.0f); r.x = prev;
    prev = fminf(fmaxf(prev, x1), x1 + 1.0f); r.y = prev;
    prev = fminf(fmaxf(prev, x2), x2 + 1.0f); r.z = prev;
    prev = fminf(fmaxf(prev, x3), x3 + 1.0f); r.w = prev;
    __stcs(&o[0], r);
    prev = fminf(fmaxf(prev, x4), x4 + 1.0f); r.x = prev;
    prev = fminf(fmaxf(prev, x5), x5 + 1.0f); r.y = prev;
    prev = fminf(fmaxf(prev, x6), x6 + 1.0f); r.z = prev;
    prev = fminf(fmaxf(prev, x7), x7 + 1.0f); r.w = prev;
    __stcs(&o[1], r);

    // new_state appended after T outputs, if present
    if (base + ITEMS == n && out_size > n) out[n] = prev;
}

extern "C" void kernel_launch(void* const* d_in, const int* in_sizes, int n_in,
                              void* d_out, int out_size) {
    const float* in  = (const float*)d_in[0];   // inputs [1, T]
    const float* stt = (const float*)d_in[1];   // state  [1, 1]
    const float* kw  = (const float*)d_in[2];   // kernel [1, 1]
    float* out = (float*)d_out;

    int n  = in_sizes[0];
    int nb = n / CHUNK;                         // 2^23 / 4096 = 2048 tiles

    k_reset<<<(nb + 255) / 256, 256>>>(nb);
    k_scan<<<nb, BLOCK>>>(in, kw, stt, out, n, out_size);
}

// round 16
// speedup vs baseline: 2.6468x; 2.6468x over previous
#include <cuda_runtime.h>
#include <math_constants.h>

// PhiCell hysteresis scan: out_i = clamp(out_{i-1}, x_i, x_i + 1), x_i = in_i*k.
// Clamp maps compose associatively -> 3-pass scan (measured-best structure).
// R13: R1 skeleton + halved dependency chains (2 independent absorb chains in
// phase1/phase3; split output recurrence in phase3 via mid-point restart map).

#define BLOCK 256
#define ITEMS 16
#define CHUNK (BLOCK * ITEMS)   // 4096 elements per block
#define MAXB  2048

struct CH { float L, H; };

__device__ __forceinline__ CH ch_id() {
    CH r; r.L = -CUDART_INF_F; r.H = CUDART_INF_F; return r;
}
// compose: apply a FIRST, then b
__device__ __forceinline__ CH ch_comp(CH a, CH b) {
    CH r;
    r.L = fminf(fmaxf(a.L, b.L), b.H);
    r.H = fminf(fmaxf(a.H, b.L), b.H);
    return r;
}

__device__ float2 g_part[MAXB];
__device__ float2 g_excl[MAXB];

__device__ __forceinline__ CH warp_incl_scan(CH v, int lane) {
#pragma unroll
    for (int off = 1; off < 32; off <<= 1) {
        float pl = __shfl_up_sync(0xffffffffu, v.L, off);
        float ph = __shfl_up_sync(0xffffffffu, v.H, off);
        if (lane >= off) { CH p; p.L = pl; p.H = ph; v = ch_comp(p, v); }
    }
    return v;
}

// exclusive composite of all lower-threadIdx threads (identity for t==0)
__device__ CH block_excl_scan(CH v) {
    __shared__ CH ws[BLOCK / 32];
    int lane = threadIdx.x & 31;
    int wid  = threadIdx.x >> 5;

    CH vi = warp_incl_scan(v, lane);
    if (lane == 31) ws[wid] = vi;
    __syncthreads();
    if (wid == 0) {
        CH w = (lane < BLOCK / 32) ? ws[lane] : ch_id();
        w = warp_incl_scan(w, lane);
        if (lane < BLOCK / 32) ws[lane] = w;
    }
    __syncthreads();
    CH wp = (wid > 0) ? ws[wid - 1] : ch_id();

    float pl = __shfl_up_sync(0xffffffffu, vi.L, 1);
    float ph = __shfl_up_sync(0xffffffffu, vi.H, 1);
    CH ve = ch_id();
    if (lane > 0) { ve.L = pl; ve.H = ph; }
    return ch_comp(wp, ve);
}

__device__ __forceinline__ void absorb(CH& c, float a) {
    float ap = a + 1.0f;
    c.L = fminf(fmaxf(c.L, a), ap);
    c.H = fminf(fmaxf(c.H, a), ap);
}

// Phase 1: per-block composite (two independent chains for ILP)
__global__ void __launch_bounds__(BLOCK)
k_phase1(const float* __restrict__ in, const float* __restrict__ kw) {
    float k = __ldg(kw);
    int base = blockIdx.x * CHUNK + threadIdx.x * ITEMS;
    const float4* p = reinterpret_cast<const float4*>(in + base);

    float4 v0 = __ldg(&p[0]);
    float4 v1 = __ldg(&p[1]);
    float4 v2 = __ldg(&p[2]);
    float4 v3 = __ldg(&p[3]);

    CH cA = ch_id(), cB = ch_id();
    absorb(cA, v0.x * k); absorb(cB, v2.x * k);
    absorb(cA, v0.y * k); absorb(cB, v2.y * k);
    absorb(cA, v0.z * k); absorb(cB, v2.z * k);
    absorb(cA, v0.w * k); absorb(cB, v2.w * k);
    absorb(cA, v1.x * k); absorb(cB, v3.x * k);
    absorb(cA, v1.y * k); absorb(cB, v3.y * k);
    absorb(cA, v1.z * k); absorb(cB, v3.z * k);
    absorb(cA, v1.w * k); absorb(cB, v3.w * k);
    CH c = ch_comp(cA, cB);

    CH e = block_excl_scan(c);
    if (threadIdx.x == BLOCK - 1) {
        CH t = ch_comp(e, c);
        g_part[blockIdx.x] = make_float2(t.L, t.H);
    }
}

// Phase 2: exclusive scan of block composites (single block)
__global__ void __launch_bounds__(BLOCK)
k_phase2(int nb) {
    int t = threadIdx.x;
    const int P = MAXB / BLOCK;               // 8
    CH loc[P];
    CH c = ch_id();
#pragma unroll
    for (int j = 0; j < P; j++) {
        int i = t * P + j;
        CH x = ch_id();
        if (i < nb) { float2 f = g_part[i]; x.L = f.x; x.H = f.y; }
        c = ch_comp(c, x);
        loc[j] = c;                           // local inclusive
    }
    CH te = block_excl_scan(c);
#pragma unroll
    for (int j = 0; j < P; j++) {
        int i = t * P + j;
        if (i < nb) {
            CH e = (j == 0) ? te : ch_comp(te, loc[j - 1]);
            g_excl[i] = make_float2(e.L, e.H);
        }
    }
}

// Phase 3: apply prefixes, split output recurrence (two concurrent chains)
__global__ void __launch_bounds__(BLOCK)
k_phase3(const float* __restrict__ in, const float* __restrict__ kw,
         const float* __restrict__ stt, float* __restrict__ out,
         int n, int out_size) {
    float k  = __ldg(kw);
    int base = blockIdx.x * CHUNK + threadIdx.x * ITEMS;
    const float4* p = reinterpret_cast<const float4*>(in + base);

    float4 v0 = __ldg(&p[0]);
    float4 v1 = __ldg(&p[1]);
    float4 v2 = __ldg(&p[2]);
    float4 v3 = __ldg(&p[3]);
    float a0 = v0.x * k, a1 = v0.y * k, a2 = v0.z * k, a3 = v0.w * k;
    float a4 = v1.x * k, a5 = v1.y * k, a6 = v1.z * k, a7 = v1.w * k;
    float b0 = v2.x * k, b1 = v2.y * k, b2 = v2.z * k, b3 = v2.w * k;
    float b4 = v3.x * k, b5 = v3.y * k, b6 = v3.z * k, b7 = v3.w * k;

    // two independent composite chains
    CH cA = ch_id(), cB = ch_id();
    absorb(cA, a0); absorb(cB, b0);
    absorb(cA, a1); absorb(cB, b1);
    absorb(cA, a2); absorb(cB, b2);
    absorb(cA, a3); absorb(cB, b3);
    absorb(cA, a4); absorb(cB, b4);
    absorb(cA, a5); absorb(cB, b5);
    absorb(cA, a6); absorb(cB, b6);
    absorb(cA, a7); absorb(cB, b7);
    CH c = ch_comp(cA, cB);

    CH e = block_excl_scan(c);

    float2 be2 = g_excl[blockIdx.x];
    CH be; be.L = be2.x; be.H = be2.y;
    CH my  = ch_comp(be, e);                  // map for out[base-1]
    CH mid = ch_comp(my, cA);                 // map for out[base+7]

    float s0 = __ldg(stt);
    float pa = fminf(fmaxf(s0, my.L),  my.H);   // restart for elems 0..7
    float pb = fminf(fmaxf(s0, mid.L), mid.H);  // restart for elems 8..15

    // two concurrent output recurrence chains (interleaved for ILP)
    float4 r0, r1, r2, r3;
    pa = fminf(fmaxf(pa, a0), a0 + 1.0f); r0.x = pa;
    pb = fminf(fmaxf(pb, b0), b0 + 1.0f); r2.x = pb;
    pa = fminf(fmaxf(pa, a1), a1 + 1.0f); r0.y = pa;
    pb = fminf(fmaxf(pb, b1), b1 + 1.0f); r2.y = pb;
    pa = fminf(fmaxf(pa, a2), a2 + 1.0f); r0.z = pa;
    pb = fminf(fmaxf(pb, b2), b2 + 1.0f); r2.z = pb;
    pa = fminf(fmaxf(pa, a3), a3 + 1.0f); r0.w = pa;
    pb = fminf(fmaxf(pb, b3), b3 + 1.0f); r2.w = pb;
    pa = fminf(fmaxf(pa, a4), a4 + 1.0f); r1.x = pa;
    pb = fminf(fmaxf(pb, b4), b4 + 1.0f); r3.x = pb;
    pa = fminf(fmaxf(pa, a5), a5 + 1.0f); r1.y = pa;
    pb = fminf(fmaxf(pb, b5), b5 + 1.0f); r3.y = pb;
    pa = fminf(fmaxf(pa, a6), a6 + 1.0f); r1.z = pa;
    pb = fminf(fmaxf(pb, b6), b6 + 1.0f); r3.z = pb;
    pa = fminf(fmaxf(pa, a7), a7 + 1.0f); r1.w = pa;
    pb = fminf(fmaxf(pb, b7), b7 + 1.0f); r3.w = pb;

    float4* o = reinterpret_cast<float4*>(out + base);
    __stcs(&o[0], r0);
    __stcs(&o[1], r1);
    __stcs(&o[2], r2);
    __stcs(&o[3], r3);

    // new_state appended after T outputs, if present
    if (base + ITEMS == n && out_size > n) out[n] = pb;
}

extern "C" void kernel_launch(void* const* d_in, const int* in_sizes, int n_in,
                              void* d_out, int out_size) {
    const float* in  = (const float*)d_in[0];   // inputs [1, T]
    const float* stt = (const float*)d_in[1];   // state  [1, 1]
    const float* kw  = (const float*)d_in[2];   // kernel [1, 1]
    float* out = (float*)d_out;

    int n  = in_sizes[0];
    int nb = n / CHUNK;                         // 2^23 / 4096 = 2048 blocks

    k_phase1<<<nb, BLOCK>>>(in, kw);
    k_phase2<<<1, BLOCK>>>(nb);
    k_phase3<<<nb, BLOCK>>>(in, kw, stt, out, n, out_size);
}